// round 2
// baseline (speedup 1.0000x reference)
#include <cuda_runtime.h>
#include <cstddef>

// Problem constants
#define Bn 8
#define Tn 512
#define Nn 64
#define Hn 256   // I == H == 256, so one projection kernel shape serves both layers

// ---------------------------------------------------------------------------
// Scratch (device globals: allocation-free rule)
// ---------------------------------------------------------------------------
__device__ float g_xin[(size_t)Bn * Tn * Nn * Hn];   // per-layer input projections
__device__ float g_y0 [(size_t)Bn * Tn * Nn * Hn];   // layer-0 outputs
__device__ float g_h[2][Bn * Nn * Hn];               // double-buffered hidden state
__device__ volatile unsigned int g_flags[64];        // grid-barrier flags (1 per block)

__global__ void reset_kernel() {
    if (threadIdx.x < 64) g_flags[threadIdx.x] = 0u;
}

// ---------------------------------------------------------------------------
// Projection: g_xin[b, m, j] = sum_i X[b, m, i] * W[b, j, i] + b_ih[b,j] + b_hh[b,j]
//   X = x (layer 0) or g_y0 (layer 1); M = T*N = 32768, K = 256, J = 256
//   grid (512 mtiles, 4 jtiles, 8 b), 256 threads, 64x64 tile, micro 4x4
// ---------------------------------------------------------------------------
__global__ __launch_bounds__(256) void proj_kernel(
    const float* __restrict__ Xext,
    const float* __restrict__ W,
    const float* __restrict__ bih,
    const float* __restrict__ bhh)
{
    __shared__ float Xs[64][33];
    __shared__ float Ws[64][33];

    const float* X = Xext ? Xext : g_y0;
    const int mt = blockIdx.x, jt = blockIdx.y, b = blockIdx.z;
    const int lin = threadIdx.x;
    const int tx = lin & 15, ty = lin >> 4;

    const float* Xb = X + ((size_t)b * (Tn * Nn) + mt * 64) * 256;
    const float* Wb = W + ((size_t)b * 256 + jt * 64) * 256;

    float acc[4][4] = {};

    for (int kk = 0; kk < 256; kk += 32) {
#pragma unroll
        for (int r = 0; r < 2; ++r) {
            int f   = lin + r * 256;        // 512 float4 slots per tile
            int row = f >> 3;
            int kc  = (f & 7) << 2;
            float4 xv = *(const float4*)(Xb + (size_t)row * 256 + kk + kc);
            Xs[row][kc] = xv.x; Xs[row][kc + 1] = xv.y;
            Xs[row][kc + 2] = xv.z; Xs[row][kc + 3] = xv.w;
            float4 wv = *(const float4*)(Wb + (size_t)row * 256 + kk + kc);
            Ws[row][kc] = wv.x; Ws[row][kc + 1] = wv.y;
            Ws[row][kc + 2] = wv.z; Ws[row][kc + 3] = wv.w;
        }
        __syncthreads();
#pragma unroll
        for (int k = 0; k < 32; ++k) {
            float xv[4], wv[4];
#pragma unroll
            for (int i = 0; i < 4; ++i) xv[i] = Xs[ty * 4 + i][k];
#pragma unroll
            for (int j = 0; j < 4; ++j) wv[j] = Ws[tx + 16 * j][k];
#pragma unroll
            for (int i = 0; i < 4; ++i)
#pragma unroll
                for (int j = 0; j < 4; ++j)
                    acc[i][j] += xv[i] * wv[j];
        }
        __syncthreads();
    }

    const size_t mbase = (size_t)b * (Tn * Nn) + mt * 64 + ty * 4;
#pragma unroll
    for (int j = 0; j < 4; ++j) {
        int jg = jt * 64 + tx + 16 * j;
        float bias = bih[b * 256 + jg] + bhh[b * 256 + jg];
#pragma unroll
        for (int i = 0; i < 4; ++i)
            g_xin[(mbase + i) * 256 + jg] = acc[i][j] + bias;
    }
}

// ---------------------------------------------------------------------------
// Recurrence: 512 sequential steps, persistent 64-block kernel w/ grid barrier.
//   h_new = tanh(xin[t] + h @ w_hh^T)
//   grid (8 jtiles, 8 b), 128 threads, per-block tile n=64 x j=32, micro 4x4
//   SMEM: w slice [32][257] (resident), h staged [64][257] per step
// ---------------------------------------------------------------------------
__global__ __launch_bounds__(128) void rec_kernel(
    const float* __restrict__ hx,     // [B, L, N, H]
    const float* __restrict__ whh,    // [B, H, H]
    float* __restrict__ yext,         // layer outputs (nullptr -> g_y0)
    float* __restrict__ hn,           // [B, L, N, H] final hidden
    int layer)
{
    extern __shared__ float sm[];
    float* w_s = sm;                  // [32][257]
    float* h_s = sm + 32 * 257;       // [64][257]

    const int jt  = blockIdx.x, b = blockIdx.y;
    const int lin = threadIdx.x;
    const int tx  = lin & 7, ty = lin >> 3;   // tx 0..7 (j), ty 0..15 (n)
    const int bid = b * 8 + jt;

    float* y = yext ? yext : g_y0;

    // Load w_hh slice once: rows j = jt*32 .. jt*32+31, k = 0..255
    const float* wb = whh + ((size_t)b * 256 + jt * 32) * 256;
    for (int f = lin; f < 2048; f += 128) {       // 2048 float4
        int row = f >> 6, kc = (f & 63) << 2;
        float4 v = *(const float4*)(wb + (size_t)row * 256 + kc);
        float* d = w_s + row * 257 + kc;
        d[0] = v.x; d[1] = v.y; d[2] = v.z; d[3] = v.w;
    }

    const float* h0 = hx + ((size_t)(b * 2 + layer)) * Nn * Hn;

    const float* hp0 = h_s + (ty * 4 + 0) * 257;
    const float* hp1 = h_s + (ty * 4 + 1) * 257;
    const float* hp2 = h_s + (ty * 4 + 2) * 257;
    const float* hp3 = h_s + (ty * 4 + 3) * 257;
    const float* wp0 = w_s + (tx +  0) * 257;
    const float* wp1 = w_s + (tx +  8) * 257;
    const float* wp2 = w_s + (tx + 16) * 257;
    const float* wp3 = w_s + (tx + 24) * 257;

    for (int t = 0; t < Tn; ++t) {
        // Stage full h[64][256] for this instance into SMEM
        const float* hsrc = (t == 0) ? h0 : (g_h[(t - 1) & 1] + (size_t)b * Nn * Hn);
        for (int f = lin; f < 4096; f += 128) {   // 4096 float4
            int row = f >> 6, kc = (f & 63) << 2;
            float4 v = *(const float4*)(hsrc + (size_t)row * 256 + kc);
            float* d = h_s + row * 257 + kc;
            d[0] = v.x; d[1] = v.y; d[2] = v.z; d[3] = v.w;
        }
        __syncthreads();

        float acc[4][4] = {};
#pragma unroll 8
        for (int k = 0; k < 256; ++k) {
            float hv[4], wv[4];
            hv[0] = hp0[k]; hv[1] = hp1[k]; hv[2] = hp2[k]; hv[3] = hp3[k];
            wv[0] = wp0[k]; wv[1] = wp1[k]; wv[2] = wp2[k]; wv[3] = wp3[k];
#pragma unroll
            for (int i = 0; i < 4; ++i)
#pragma unroll
                for (int j = 0; j < 4; ++j)
                    acc[i][j] += hv[i] * wv[j];
        }

        // Epilogue: h_new = tanh(acc + xin), write y, h_next (and hn at t=T-1)
        const float* xt   = g_xin + ((size_t)b * Tn + t) * Nn * Hn;
        float*       yt   = y     + ((size_t)b * Tn + t) * Nn * Hn;
        float*       hdst = g_h[t & 1] + (size_t)b * Nn * Hn;
#pragma unroll
        for (int i = 0; i < 4; ++i) {
            int n = ty * 4 + i;
#pragma unroll
            for (int j = 0; j < 4; ++j) {
                int jg = jt * 32 + tx + 8 * j;
                float v = tanhf(acc[i][j] + xt[(size_t)n * Hn + jg]);
                yt[(size_t)n * Hn + jg]   = v;
                hdst[(size_t)n * Hn + jg] = v;
                if (t == Tn - 1)
                    hn[((size_t)(b * 2 + layer) * Nn + n) * Hn + jg] = v;
            }
        }

        // Grid barrier: per-block flag array, no contended atomic.
        __threadfence();
        __syncthreads();
        if (lin == 0) g_flags[bid] = (unsigned)(t + 1);
        if (lin < 64) {
            while (g_flags[lin] < (unsigned)(t + 1)) { }
        }
        __threadfence();
        __syncthreads();
    }
}

// ---------------------------------------------------------------------------
// Launch
// ---------------------------------------------------------------------------
extern "C" void kernel_launch(void* const* d_in, const int* in_sizes, int n_in,
                              void* d_out, int out_size)
{
    const float* x    = (const float*)d_in[0];
    const float* hx   = (const float*)d_in[1];
    const float* wih0 = (const float*)d_in[2];
    const float* whh0 = (const float*)d_in[3];
    const float* bih0 = (const float*)d_in[4];
    const float* bhh0 = (const float*)d_in[5];
    const float* wih1 = (const float*)d_in[6];
    const float* whh1 = (const float*)d_in[7];
    const float* bih1 = (const float*)d_in[8];
    const float* bhh1 = (const float*)d_in[9];

    float* out = (float*)d_out;                          // [B, T, N, H]
    float* hn  = out + (size_t)Bn * Tn * Nn * Hn;        // [B, L, N, H]

    const size_t rec_smem = (size_t)(32 * 257 + 64 * 257) * sizeof(float);  // 98688 B
    cudaFuncSetAttribute(rec_kernel, cudaFuncAttributeMaxDynamicSharedMemorySize,
                         (int)rec_smem);

    dim3 pgrid(Tn * Nn / 64, Hn / 64, Bn);   // (512, 4, 8)
    dim3 rgrid(8, Bn);                        // 64 blocks, all resident

    // Layer 0
    reset_kernel<<<1, 64>>>();
    proj_kernel<<<pgrid, 256>>>(x, wih0, bih0, bhh0);
    rec_kernel<<<rgrid, 128, rec_smem>>>(hx, whh0, nullptr, hn, 0);

    // Layer 1
    reset_kernel<<<1, 64>>>();
    proj_kernel<<<pgrid, 256>>>(nullptr, wih1, bih1, bhh1);
    rec_kernel<<<rgrid, 128, rec_smem>>>(hx, whh1, out, hn, 1);
}

// round 4
// speedup vs baseline: 1.1873x; 1.1873x over previous
#include <cuda_runtime.h>
#include <cstddef>

// Problem constants
#define Bn 8
#define Tn 512
#define Nn 64
#define Hn 256   // I == H == 256

// ---------------------------------------------------------------------------
// Scratch (device globals: allocation-free rule)
// ---------------------------------------------------------------------------
__device__ float g_xin[(size_t)Bn * Tn * Nn * Hn];   // per-layer input projections
__device__ float g_y0 [(size_t)Bn * Tn * Nn * Hn];   // layer-0 outputs
__device__ float g_h[2][Bn * Nn * Hn];               // double-buffered hidden, K-MAJOR [b][k][n]

// ---------------------------------------------------------------------------
// Transpose hx[b, layer, n, k] -> g_h[1][b, k, n]   (t=0 reads buffer (0-1)&1 = 1)
// ---------------------------------------------------------------------------
__global__ void htrans_kernel(const float* __restrict__ hx, int layer) {
    const int b = blockIdx.x;
    const float* src = hx + (size_t)(b * 2 + layer) * (Nn * Hn);
    float* dst = g_h[1] + (size_t)b * (Nn * Hn);
    for (int idx = threadIdx.x; idx < Nn * Hn; idx += blockDim.x) {
        int n = idx >> 8, k = idx & 255;
        dst[k * Nn + n] = src[idx];
    }
}

// ---------------------------------------------------------------------------
// Projection: g_xin[b, m, j] = sum_i X[b, m, i] * W[b, j, i] + b_ih[b,j] + b_hh[b,j]
//   M = T*N = 32768, K = 256, J = 256; 64x64 tile, micro 4x4, 256 threads
// ---------------------------------------------------------------------------
__global__ __launch_bounds__(256) void proj_kernel(
    const float* __restrict__ Xext,
    const float* __restrict__ W,
    const float* __restrict__ bih,
    const float* __restrict__ bhh)
{
    __shared__ float Xs[64][33];
    __shared__ float Ws[64][33];

    const float* X = Xext ? Xext : g_y0;
    const int mt = blockIdx.x, jt = blockIdx.y, b = blockIdx.z;
    const int lin = threadIdx.x;
    const int tx = lin & 15, ty = lin >> 4;

    const float* Xb = X + ((size_t)b * (Tn * Nn) + mt * 64) * 256;
    const float* Wb = W + ((size_t)b * 256 + jt * 64) * 256;

    float acc[4][4] = {};

    for (int kk = 0; kk < 256; kk += 32) {
#pragma unroll
        for (int r = 0; r < 2; ++r) {
            int f   = lin + r * 256;
            int row = f >> 3;
            int kc  = (f & 7) << 2;
            float4 xv = *(const float4*)(Xb + (size_t)row * 256 + kk + kc);
            Xs[row][kc] = xv.x; Xs[row][kc + 1] = xv.y;
            Xs[row][kc + 2] = xv.z; Xs[row][kc + 3] = xv.w;
            float4 wv = *(const float4*)(Wb + (size_t)row * 256 + kk + kc);
            Ws[row][kc] = wv.x; Ws[row][kc + 1] = wv.y;
            Ws[row][kc + 2] = wv.z; Ws[row][kc + 3] = wv.w;
        }
        __syncthreads();
#pragma unroll
        for (int k = 0; k < 32; ++k) {
            float xv[4], wv[4];
#pragma unroll
            for (int i = 0; i < 4; ++i) xv[i] = Xs[ty * 4 + i][k];
#pragma unroll
            for (int j = 0; j < 4; ++j) wv[j] = Ws[tx + 16 * j][k];
#pragma unroll
            for (int i = 0; i < 4; ++i)
#pragma unroll
                for (int j = 0; j < 4; ++j)
                    acc[i][j] += xv[i] * wv[j];
        }
        __syncthreads();
    }

    const size_t mbase = (size_t)b * (Tn * Nn) + mt * 64 + ty * 4;
#pragma unroll
    for (int j = 0; j < 4; ++j) {
        int jg = jt * 64 + tx + 16 * j;
        float bias = bih[b * 256 + jg] + bhh[b * 256 + jg];
#pragma unroll
        for (int i = 0; i < 4; ++i)
            g_xin[(mbase + i) * 256 + jg] = acc[i][j] + bias;
    }
}

// ---------------------------------------------------------------------------
// Recurrence: 512 sequential steps. One 8-CTA CLUSTER per fused instance.
//   h_new = tanh(xin[t] + h @ w_hh^T)
//   grid (8 jtiles, 8 b), cluster (8,1,1), 128 threads
//   per-CTA tile: n=64 x j=32, micro 4(n) x 4(j, contiguous)
//   SMEM (k-major): w_s[256][36] resident, h_s[256][68] staged per step
// ---------------------------------------------------------------------------
__global__ __launch_bounds__(128) __cluster_dims__(8, 1, 1)
void rec_kernel(
    const float* __restrict__ whh,    // [B, H, H]
    float* __restrict__ yext,         // layer outputs (nullptr -> g_y0)
    float* __restrict__ hn,           // [B, L, N, H] final hidden
    int layer)
{
    extern __shared__ float sm[];
    float* w_s = sm;                  // [256][36]  (k-major, j fast)
    float* h_s = sm + 256 * 36;       // [256][68]  (k-major, n fast)

    const int jt  = blockIdx.x, b = blockIdx.y;
    const int lin = threadIdx.x;
    const int tx  = lin & 7, ty = lin >> 3;   // tx 0..7 (j/4), ty 0..15 (n/4)
    const int tx4 = tx * 4, ty4 = ty * 4;

    float* y = yext ? yext : g_y0;

    // Load w_hh slice once, transposed into k-major: w_s[k][j] = whh[b][jt*32+j][k]
    const float* wb = whh + ((size_t)b * 256 + jt * 32) * 256;
    for (int f = lin; f < 2048; f += 128) {          // 2048 float4 reads
        int j = f >> 6, kc = (f & 63) << 2;
        float4 v = *(const float4*)(wb + (size_t)j * 256 + kc);
        w_s[(kc + 0) * 36 + j] = v.x;
        w_s[(kc + 1) * 36 + j] = v.y;
        w_s[(kc + 2) * 36 + j] = v.z;
        w_s[(kc + 3) * 36 + j] = v.w;
    }

    const int jgbase = jt * 32 + tx4;

    for (int t = 0; t < Tn; ++t) {
        // Stage h (k-major) for this instance: g_h[(t-1)&1][b][k][n] -> h_s[k][n]
        const float* hsrc = g_h[(t + 1) & 1] + (size_t)b * (Nn * Hn);
#pragma unroll 4
        for (int f = lin; f < 4096; f += 128) {      // 4096 float4
            int k = f >> 4, nc = (f & 15) << 2;
            float4 v = __ldcg((const float4*)(hsrc + (size_t)k * Nn + nc));
            *(float4*)(h_s + k * 68 + nc) = v;
        }
        __syncthreads();

        float acc[4][4] = {};
#pragma unroll 8
        for (int k = 0; k < 256; ++k) {
            float4 hv = *(const float4*)(h_s + k * 68 + ty4);
            float4 wv = *(const float4*)(w_s + k * 36 + tx4);
            acc[0][0] += hv.x * wv.x; acc[0][1] += hv.x * wv.y;
            acc[0][2] += hv.x * wv.z; acc[0][3] += hv.x * wv.w;
            acc[1][0] += hv.y * wv.x; acc[1][1] += hv.y * wv.y;
            acc[1][2] += hv.y * wv.z; acc[1][3] += hv.y * wv.w;
            acc[2][0] += hv.z * wv.x; acc[2][1] += hv.z * wv.y;
            acc[2][2] += hv.z * wv.z; acc[2][3] += hv.z * wv.w;
            acc[3][0] += hv.w * wv.x; acc[3][1] += hv.w * wv.y;
            acc[3][2] += hv.w * wv.z; acc[3][3] += hv.w * wv.w;
        }

        // Epilogue: v = tanh(acc + xin[t]); write y (STG.128), h_next (k-major), hn at end
        const float* xt   = g_xin + ((size_t)b * Tn + t) * (Nn * Hn);
        float*       yt   = y     + ((size_t)b * Tn + t) * (Nn * Hn);
        float*       hdst = g_h[t & 1] + (size_t)b * (Nn * Hn);
#pragma unroll
        for (int i = 0; i < 4; ++i) {
            int n = ty4 + i;
            float4 xv = *(const float4*)(xt + (size_t)n * Hn + jgbase);
            float4 v;
            v.x = tanhf(acc[i][0] + xv.x);
            v.y = tanhf(acc[i][1] + xv.y);
            v.z = tanhf(acc[i][2] + xv.z);
            v.w = tanhf(acc[i][3] + xv.w);
            *(float4*)(yt + (size_t)n * Hn + jgbase) = v;
            hdst[(jgbase + 0) * Nn + n] = v.x;
            hdst[(jgbase + 1) * Nn + n] = v.y;
            hdst[(jgbase + 2) * Nn + n] = v.z;
            hdst[(jgbase + 3) * Nn + n] = v.w;
            if (t == Tn - 1)
                *(float4*)(hn + ((size_t)(b * 2 + layer) * Nn + n) * Hn + jgbase) = v;
        }

        // Cluster barrier: release h stores of step t, acquire peers' before t+1.
        asm volatile("barrier.cluster.arrive.aligned;" ::: "memory");
        asm volatile("barrier.cluster.wait.aligned;"   ::: "memory");
    }
}

// ---------------------------------------------------------------------------
// Launch
// ---------------------------------------------------------------------------
extern "C" void kernel_launch(void* const* d_in, const int* in_sizes, int n_in,
                              void* d_out, int out_size)
{
    const float* x    = (const float*)d_in[0];
    const float* hx   = (const float*)d_in[1];
    const float* wih0 = (const float*)d_in[2];
    const float* whh0 = (const float*)d_in[3];
    const float* bih0 = (const float*)d_in[4];
    const float* bhh0 = (const float*)d_in[5];
    const float* wih1 = (const float*)d_in[6];
    const float* whh1 = (const float*)d_in[7];
    const float* bih1 = (const float*)d_in[8];
    const float* bhh1 = (const float*)d_in[9];

    float* out = (float*)d_out;                          // [B, T, N, H]
    float* hn  = out + (size_t)Bn * Tn * Nn * Hn;        // [B, L, N, H]

    const size_t rec_smem = (size_t)(256 * 36 + 256 * 68) * sizeof(float);  // 106496 B
    static int attr_set = 0;
    cudaFuncSetAttribute(rec_kernel, cudaFuncAttributeMaxDynamicSharedMemorySize,
                         (int)rec_smem);
    (void)attr_set;

    dim3 pgrid(Tn * Nn / 64, Hn / 64, Bn);   // (512, 4, 8)
    dim3 rgrid(8, Bn);                        // 64 CTAs = 8 clusters of 8

    // Layer 0
    htrans_kernel<<<Bn, 256>>>(hx, 0);
    proj_kernel<<<pgrid, 256>>>(x, wih0, bih0, bhh0);
    rec_kernel<<<rgrid, 128, rec_smem>>>(whh0, nullptr, hn, 0);

    // Layer 1
    htrans_kernel<<<Bn, 256>>>(hx, 1);
    proj_kernel<<<pgrid, 256>>>(nullptr, wih1, bih1, bhh1);
    rec_kernel<<<rgrid, 128, rec_smem>>>(whh1, out, hn, 1);
}

// round 5
// speedup vs baseline: 2.2544x; 1.8987x over previous
#include <cuda_runtime.h>
#include <cstddef>

// Problem constants
#define Bn 8
#define Tn 512
#define Nn 64
#define Hn 256   // I == H == 256

// ---------------------------------------------------------------------------
// Scratch (device globals: allocation-free rule)
// ---------------------------------------------------------------------------
__device__ float g_xin[(size_t)Bn * Tn * Nn * Hn];   // per-layer input projections
__device__ float g_y0 [(size_t)Bn * Tn * Nn * Hn];   // layer-0 outputs
// hidden state, double buffered, K-MAJOR per n-half: [2][b*2+nh][k=256][n=32]
__device__ float g_h[2][Bn * 2 * 256 * 32];

// ---------------------------------------------------------------------------
// Projection: g_xin[b, m, j] = sum_i X[b, m, i] * W[b, j, i] + b_ih[b,j] + b_hh[b,j]
//   M = T*N = 32768, K = 256, J = 256; 64x64 tile, micro 4x4, 256 threads
// ---------------------------------------------------------------------------
__global__ __launch_bounds__(256) void proj_kernel(
    const float* __restrict__ Xext,
    const float* __restrict__ W,
    const float* __restrict__ bih,
    const float* __restrict__ bhh)
{
    __shared__ float Xs[64][33];
    __shared__ float Ws[64][33];

    const float* X = Xext ? Xext : g_y0;
    const int mt = blockIdx.x, jt = blockIdx.y, b = blockIdx.z;
    const int lin = threadIdx.x;
    const int tx = lin & 15, ty = lin >> 4;

    const float* Xb = X + ((size_t)b * (Tn * Nn) + mt * 64) * 256;
    const float* Wb = W + ((size_t)b * 256 + jt * 64) * 256;

    float acc[4][4] = {};

    for (int kk = 0; kk < 256; kk += 32) {
#pragma unroll
        for (int r = 0; r < 2; ++r) {
            int f   = lin + r * 256;
            int row = f >> 3;
            int kc  = (f & 7) << 2;
            float4 xv = *(const float4*)(Xb + (size_t)row * 256 + kk + kc);
            Xs[row][kc] = xv.x; Xs[row][kc + 1] = xv.y;
            Xs[row][kc + 2] = xv.z; Xs[row][kc + 3] = xv.w;
            float4 wv = *(const float4*)(Wb + (size_t)row * 256 + kk + kc);
            Ws[row][kc] = wv.x; Ws[row][kc + 1] = wv.y;
            Ws[row][kc + 2] = wv.z; Ws[row][kc + 3] = wv.w;
        }
        __syncthreads();
#pragma unroll
        for (int k = 0; k < 32; ++k) {
            float xv[4], wv[4];
#pragma unroll
            for (int i = 0; i < 4; ++i) xv[i] = Xs[ty * 4 + i][k];
#pragma unroll
            for (int j = 0; j < 4; ++j) wv[j] = Ws[tx + 16 * j][k];
#pragma unroll
            for (int i = 0; i < 4; ++i)
#pragma unroll
                for (int j = 0; j < 4; ++j)
                    acc[i][j] += xv[i] * wv[j];
        }
        __syncthreads();
    }

    const size_t mbase = (size_t)b * (Tn * Nn) + mt * 64 + ty * 4;
#pragma unroll
    for (int j = 0; j < 4; ++j) {
        int jg = jt * 64 + tx + 16 * j;
        float bias = bih[b * 256 + jg] + bhh[b * 256 + jg];
#pragma unroll
        for (int i = 0; i < 4; ++i)
            g_xin[(mbase + i) * 256 + jg] = acc[i][j] + bias;
    }
}

// ---------------------------------------------------------------------------
// Recurrence: 512 sequential steps.
//   128 CTAs = 16 clusters of 8. Cluster = (instance b, n-half nh) x 8 j-tiles.
//   Per-CTA tile: n=32 x j=32 x k=256 (262144 FMA -> 4096 cyc FFMA floor/SM).
//   256 threads, micro 2(n) x 2(j). SMEM k-major: w_s[256][36], h_s[256][36].
//   h exchanged via global k-major buffer + cluster barrier per step.
// ---------------------------------------------------------------------------
__global__ __launch_bounds__(256) __cluster_dims__(8, 1, 1)
void rec_kernel(
    const float* __restrict__ hx,     // [B, L, N, H]
    const float* __restrict__ whh,    // [B, H, H]
    float* __restrict__ yext,         // layer outputs (nullptr -> g_y0)
    float* __restrict__ hn,           // [B, L, N, H] final hidden
    int layer)
{
    extern __shared__ float sm[];
    float* w_s = sm;                  // [256][36]  k-major, j fast
    float* h_s = sm + 256 * 36;       // [256][36]  k-major, n fast (32 + pad)

    const int jt  = blockIdx.x;
    const int bnh = blockIdx.y;             // b*2 + nh
    const int b   = bnh >> 1, nh = bnh & 1;
    const int lin = threadIdx.x;
    const int tx  = lin & 15, ty = lin >> 4;   // tx: j/2 (0..15), ty: n/2 (0..15)
    const int tx2 = tx * 2, ty2 = ty * 2;

    float* y = yext ? yext : g_y0;

    // Resident weight slice, transposed k-major: w_s[k][j] = whh[b][jt*32+j][k]
    const float* wb = whh + ((size_t)b * 256 + jt * 32) * 256;
    for (int f = lin; f < 2048; f += 256) {       // 2048 float4
        int j = f >> 6, kc = (f & 63) << 2;
        float4 v = *(const float4*)(wb + (size_t)j * 256 + kc);
        w_s[(kc + 0) * 36 + j] = v.x;
        w_s[(kc + 1) * 36 + j] = v.y;
        w_s[(kc + 2) * 36 + j] = v.z;
        w_s[(kc + 3) * 36 + j] = v.w;
    }

    // t=0: stage h from hx with on-the-fly transpose (one-time)
    const float* h0 = hx + (size_t)(b * 2 + layer) * Nn * Hn + nh * 32 * 256;
    for (int f = lin; f < 8192; f += 256) {       // 32 n x 256 k scalars
        int n = f >> 8, k = f & 255;
        h_s[k * 36 + n] = h0[n * 256 + k];
    }
    __syncthreads();

    const int jgbase = jt * 32 + tx2;
    const size_t hb_off = (size_t)bnh * 256 * 32;

    for (int t = 0; t < Tn; ++t) {
        float a00 = 0.f, a01 = 0.f, a10 = 0.f, a11 = 0.f;
#pragma unroll 8
        for (int k = 0; k < 256; ++k) {
            float2 hv = *(const float2*)(h_s + k * 36 + ty2);
            float2 wv = *(const float2*)(w_s + k * 36 + tx2);
            a00 += hv.x * wv.x; a01 += hv.x * wv.y;
            a10 += hv.y * wv.x; a11 += hv.y * wv.y;
        }

        const float* xt = g_xin + ((size_t)b * Tn + t) * (Nn * Hn) + nh * 32 * 256;
        float*       yt = y     + ((size_t)b * Tn + t) * (Nn * Hn) + nh * 32 * 256;
        float*     hdst = g_h[t & 1] + hb_off;

        float2 x0 = *(const float2*)(xt + (size_t)(ty2 + 0) * 256 + jgbase);
        float2 x1 = *(const float2*)(xt + (size_t)(ty2 + 1) * 256 + jgbase);
        float v00 = tanhf(a00 + x0.x), v01 = tanhf(a01 + x0.y);
        float v10 = tanhf(a10 + x1.x), v11 = tanhf(a11 + x1.y);

        // h store first (k-major: hdst[jg][n_local]) -> arrive -> y/hn -> wait
        *(float2*)(hdst + (size_t)(jgbase + 0) * 32 + ty2) = make_float2(v00, v10);
        *(float2*)(hdst + (size_t)(jgbase + 1) * 32 + ty2) = make_float2(v01, v11);

        asm volatile("barrier.cluster.arrive.aligned;" ::: "memory");

        *(float2*)(yt + (size_t)(ty2 + 0) * 256 + jgbase) = make_float2(v00, v01);
        *(float2*)(yt + (size_t)(ty2 + 1) * 256 + jgbase) = make_float2(v10, v11);
        if (t == Tn - 1) {
            float* hnp = hn + ((size_t)(b * 2 + layer) * Nn + nh * 32) * Hn;
            *(float2*)(hnp + (size_t)(ty2 + 0) * 256 + jgbase) = make_float2(v00, v01);
            *(float2*)(hnp + (size_t)(ty2 + 1) * 256 + jgbase) = make_float2(v10, v11);
        }

        asm volatile("barrier.cluster.wait.aligned;" ::: "memory");
        // aligned cluster barrier doubles as a CTA barrier: all threads are past
        // the compute loop, all peer h stores are visible. Restage h for t+1.
        if (t < Tn - 1) {
            const float* hsrc = g_h[t & 1] + hb_off;
#pragma unroll 8
            for (int f = lin; f < 2048; f += 256) {   // 2048 float4 = 32 KB
                int k = f >> 3, nc = (f & 7) << 2;
                float4 v = __ldcg((const float4*)(hsrc + (size_t)k * 32 + nc));
                *(float4*)(h_s + k * 36 + nc) = v;
            }
            __syncthreads();
        }
    }
}

// ---------------------------------------------------------------------------
// Launch: 4 launches total (proj, rec) x 2 layers
// ---------------------------------------------------------------------------
extern "C" void kernel_launch(void* const* d_in, const int* in_sizes, int n_in,
                              void* d_out, int out_size)
{
    const float* x    = (const float*)d_in[0];
    const float* hx   = (const float*)d_in[1];
    const float* wih0 = (const float*)d_in[2];
    const float* whh0 = (const float*)d_in[3];
    const float* bih0 = (const float*)d_in[4];
    const float* bhh0 = (const float*)d_in[5];
    const float* wih1 = (const float*)d_in[6];
    const float* whh1 = (const float*)d_in[7];
    const float* bih1 = (const float*)d_in[8];
    const float* bhh1 = (const float*)d_in[9];

    float* out = (float*)d_out;                          // [B, T, N, H]
    float* hn  = out + (size_t)Bn * Tn * Nn * Hn;        // [B, L, N, H]

    const size_t rec_smem = (size_t)(2 * 256 * 36) * sizeof(float);  // 73728 B
    cudaFuncSetAttribute(rec_kernel, cudaFuncAttributeMaxDynamicSharedMemorySize,
                         (int)rec_smem);

    dim3 pgrid(Tn * Nn / 64, Hn / 64, Bn);   // (512, 4, 8)
    dim3 rgrid(8, Bn * 2);                    // 128 CTAs = 16 clusters of 8

    // Layer 0
    proj_kernel<<<pgrid, 256>>>(x, wih0, bih0, bhh0);
    rec_kernel<<<rgrid, 256, rec_smem>>>(hx, whh0, nullptr, hn, 0);

    // Layer 1
    proj_kernel<<<pgrid, 256>>>(nullptr, wih1, bih1, bhh1);
    rec_kernel<<<rgrid, 256, rec_smem>>>(hx, whh1, out, hn, 1);
}

// round 6
// speedup vs baseline: 2.5408x; 1.1271x over previous
#include <cuda_runtime.h>
#include <cstddef>

// Problem constants
#define Bn 8
#define Tn 512
#define Nn 64
#define Hn 256   // I == H == 256

// ---------------------------------------------------------------------------
// Scratch (device globals: allocation-free rule)
// ---------------------------------------------------------------------------
__device__ float g_xin[(size_t)Bn * Tn * Nn * Hn];   // per-layer input projections
__device__ float g_y0 [(size_t)Bn * Tn * Nn * Hn];   // layer-0 outputs
// hidden state, double buffered, K-MAJOR per n-half: [2][b*2+nh][k=256][n=32]
__device__ float g_h[2][Bn * 2 * 256 * 32];

// f32x2 packed helpers -------------------------------------------------------
__device__ __forceinline__ unsigned long long dup_f32(float x) {
    unsigned long long r;
    asm("mov.b64 %0, {%1, %1};" : "=l"(r) : "f"(x));
    return r;
}
__device__ __forceinline__ void fma2(unsigned long long& acc,
                                     unsigned long long a, unsigned long long b) {
    asm("fma.rn.f32x2 %0, %1, %2, %0;" : "+l"(acc) : "l"(a), "l"(b));
}
__device__ __forceinline__ void unpack2(unsigned long long v, float& lo, float& hi) {
    asm("mov.b64 {%0, %1}, %2;" : "=f"(lo), "=f"(hi) : "l"(v));
}

// ---------------------------------------------------------------------------
// Projection: g_xin[b, m, j] = sum_i X[b, m, i] * W[b, j, i] + b_ih[b,j] + b_hh[b,j]
//   (unchanged from R5 — known good)
// ---------------------------------------------------------------------------
__global__ __launch_bounds__(256) void proj_kernel(
    const float* __restrict__ Xext,
    const float* __restrict__ W,
    const float* __restrict__ bih,
    const float* __restrict__ bhh)
{
    __shared__ float Xs[64][33];
    __shared__ float Ws[64][33];

    const float* X = Xext ? Xext : g_y0;
    const int mt = blockIdx.x, jt = blockIdx.y, b = blockIdx.z;
    const int lin = threadIdx.x;
    const int tx = lin & 15, ty = lin >> 4;

    const float* Xb = X + ((size_t)b * (Tn * Nn) + mt * 64) * 256;
    const float* Wb = W + ((size_t)b * 256 + jt * 64) * 256;

    float acc[4][4] = {};

    for (int kk = 0; kk < 256; kk += 32) {
#pragma unroll
        for (int r = 0; r < 2; ++r) {
            int f   = lin + r * 256;
            int row = f >> 3;
            int kc  = (f & 7) << 2;
            float4 xv = *(const float4*)(Xb + (size_t)row * 256 + kk + kc);
            Xs[row][kc] = xv.x; Xs[row][kc + 1] = xv.y;
            Xs[row][kc + 2] = xv.z; Xs[row][kc + 3] = xv.w;
            float4 wv = *(const float4*)(Wb + (size_t)row * 256 + kk + kc);
            Ws[row][kc] = wv.x; Ws[row][kc + 1] = wv.y;
            Ws[row][kc + 2] = wv.z; Ws[row][kc + 3] = wv.w;
        }
        __syncthreads();
#pragma unroll
        for (int k = 0; k < 32; ++k) {
            float xv[4], wv[4];
#pragma unroll
            for (int i = 0; i < 4; ++i) xv[i] = Xs[ty * 4 + i][k];
#pragma unroll
            for (int j = 0; j < 4; ++j) wv[j] = Ws[tx + 16 * j][k];
#pragma unroll
            for (int i = 0; i < 4; ++i)
#pragma unroll
                for (int j = 0; j < 4; ++j)
                    acc[i][j] += xv[i] * wv[j];
        }
        __syncthreads();
    }

    const size_t mbase = (size_t)b * (Tn * Nn) + mt * 64 + ty * 4;
#pragma unroll
    for (int j = 0; j < 4; ++j) {
        int jg = jt * 64 + tx + 16 * j;
        float bias = bih[b * 256 + jg] + bhh[b * 256 + jg];
#pragma unroll
        for (int i = 0; i < 4; ++i)
            g_xin[(mbase + i) * 256 + jg] = acc[i][j] + bias;
    }
}

// ---------------------------------------------------------------------------
// Recurrence: 512 sequential steps, packed-f32x2 mainloop.
//   128 CTAs = 16 clusters of 8. Cluster = (instance b, n-half nh) x 8 j-tiles.
//   Per-CTA tile: n=32 x j=32 x k=256. 128 threads, micro 2(n) x 4(j).
//   Per k: LDS.64 h (bcast) + LDS.128 w (2 j-pairs) + 2 dup + 4 FFMA2.
//   SMEM k-major: w_s[256][36], h_s[256][36].
// ---------------------------------------------------------------------------
__global__ __launch_bounds__(128) __cluster_dims__(8, 1, 1)
void rec_kernel(
    const float* __restrict__ hx,     // [B, L, N, H]
    const float* __restrict__ whh,    // [B, H, H]
    float* __restrict__ yext,         // layer outputs (nullptr -> g_y0)
    float* __restrict__ hn,           // [B, L, N, H] final hidden
    int layer)
{
    extern __shared__ float sm[];
    float* w_s = sm;                  // [256][36]  k-major, j fast
    float* h_s = sm + 256 * 36;       // [256][36]  k-major, n fast (32 + pad)

    const int jt  = blockIdx.x;
    const int bnh = blockIdx.y;             // b*2 + nh
    const int b   = bnh >> 1, nh = bnh & 1;
    const int lin = threadIdx.x;
    const int tx  = lin & 7,  ty = lin >> 3;   // tx: j-quad (0..7), ty: n-pair (0..15)
    const int tx4 = tx * 4,   ty2 = ty * 2;

    float* y = yext ? yext : g_y0;

    // Resident weight slice, transposed k-major: w_s[k][j] = whh[b][jt*32+j][k]
    const float* wb = whh + ((size_t)b * 256 + jt * 32) * 256;
    for (int f = lin; f < 2048; f += 128) {       // 2048 float4
        int j = f >> 6, kc = (f & 63) << 2;
        float4 v = *(const float4*)(wb + (size_t)j * 256 + kc);
        w_s[(kc + 0) * 36 + j] = v.x;
        w_s[(kc + 1) * 36 + j] = v.y;
        w_s[(kc + 2) * 36 + j] = v.z;
        w_s[(kc + 3) * 36 + j] = v.w;
    }

    // t=0: stage h from hx with on-the-fly transpose (one-time)
    const float* h0 = hx + (size_t)(b * 2 + layer) * Nn * Hn + nh * 32 * 256;
    for (int f = lin; f < 8192; f += 128) {       // 32 n x 256 k scalars
        int n = f >> 8, k = f & 255;
        h_s[k * 36 + n] = h0[n * 256 + k];
    }
    __syncthreads();

    const int jgbase = jt * 32 + tx4;
    const size_t hb_off = (size_t)bnh * 256 * 32;

    for (int t = 0; t < Tn; ++t) {
        const float* xt = g_xin + ((size_t)b * Tn + t) * (Nn * Hn) + nh * 32 * 256;
        float*       yt = y     + ((size_t)b * Tn + t) * (Nn * Hn) + nh * 32 * 256;
        float*     hdst = g_h[t & 1] + hb_off;

        // Prefetch xin[t] fragment before the GEMM so DRAM latency hides
        float4 x0 = __ldg((const float4*)(xt + (size_t)(ty2 + 0) * 256 + jgbase));
        float4 x1 = __ldg((const float4*)(xt + (size_t)(ty2 + 1) * 256 + jgbase));

        // Packed-f32x2 mainloop: acc[n][jpair]
        unsigned long long a00 = 0ull, a01 = 0ull, a10 = 0ull, a11 = 0ull;
#pragma unroll 8
        for (int k = 0; k < 256; ++k) {
            float2 hv = *(const float2*)(h_s + k * 36 + ty2);
            ulonglong2 wv = *(const ulonglong2*)(w_s + k * 36 + tx4);
            unsigned long long h0d = dup_f32(hv.x);
            unsigned long long h1d = dup_f32(hv.y);
            fma2(a00, h0d, wv.x);
            fma2(a01, h0d, wv.y);
            fma2(a10, h1d, wv.x);
            fma2(a11, h1d, wv.y);
        }

        float f00, f01, f02, f03, f10, f11, f12, f13;
        unpack2(a00, f00, f01); unpack2(a01, f02, f03);
        unpack2(a10, f10, f11); unpack2(a11, f12, f13);

        float4 v0, v1;
        v0.x = tanhf(f00 + x0.x); v0.y = tanhf(f01 + x0.y);
        v0.z = tanhf(f02 + x0.z); v0.w = tanhf(f03 + x0.w);
        v1.x = tanhf(f10 + x1.x); v1.y = tanhf(f11 + x1.y);
        v1.z = tanhf(f12 + x1.z); v1.w = tanhf(f13 + x1.w);

        // h store first (k-major: hdst[jg][n_local]) -> arrive -> y/hn -> wait
        *(float2*)(hdst + (size_t)(jgbase + 0) * 32 + ty2) = make_float2(v0.x, v1.x);
        *(float2*)(hdst + (size_t)(jgbase + 1) * 32 + ty2) = make_float2(v0.y, v1.y);
        *(float2*)(hdst + (size_t)(jgbase + 2) * 32 + ty2) = make_float2(v0.z, v1.z);
        *(float2*)(hdst + (size_t)(jgbase + 3) * 32 + ty2) = make_float2(v0.w, v1.w);

        asm volatile("barrier.cluster.arrive.aligned;" ::: "memory");

        *(float4*)(yt + (size_t)(ty2 + 0) * 256 + jgbase) = v0;
        *(float4*)(yt + (size_t)(ty2 + 1) * 256 + jgbase) = v1;
        if (t == Tn - 1) {
            float* hnp = hn + ((size_t)(b * 2 + layer) * Nn + nh * 32) * Hn;
            *(float4*)(hnp + (size_t)(ty2 + 0) * 256 + jgbase) = v0;
            *(float4*)(hnp + (size_t)(ty2 + 1) * 256 + jgbase) = v1;
        }

        asm volatile("barrier.cluster.wait.aligned;" ::: "memory");
        // aligned cluster barrier doubles as a CTA barrier; peer h stores visible.
        if (t < Tn - 1) {
            const float* hsrc = g_h[t & 1] + hb_off;
#pragma unroll 16
            for (int f = lin; f < 2048; f += 128) {   // 2048 float4 = 32 KB
                int k = f >> 3, nc = (f & 7) << 2;
                float4 v = __ldcg((const float4*)(hsrc + (size_t)k * 32 + nc));
                *(float4*)(h_s + k * 36 + nc) = v;
            }
            __syncthreads();
        }
    }
}

// ---------------------------------------------------------------------------
// Launch: 4 launches total (proj, rec) x 2 layers
// ---------------------------------------------------------------------------
extern "C" void kernel_launch(void* const* d_in, const int* in_sizes, int n_in,
                              void* d_out, int out_size)
{
    const float* x    = (const float*)d_in[0];
    const float* hx   = (const float*)d_in[1];
    const float* wih0 = (const float*)d_in[2];
    const float* whh0 = (const float*)d_in[3];
    const float* bih0 = (const float*)d_in[4];
    const float* bhh0 = (const float*)d_in[5];
    const float* wih1 = (const float*)d_in[6];
    const float* whh1 = (const float*)d_in[7];
    const float* bih1 = (const float*)d_in[8];
    const float* bhh1 = (const float*)d_in[9];

    float* out = (float*)d_out;                          // [B, T, N, H]
    float* hn  = out + (size_t)Bn * Tn * Nn * Hn;        // [B, L, N, H]

    const size_t rec_smem = (size_t)(2 * 256 * 36) * sizeof(float);  // 73728 B
    cudaFuncSetAttribute(rec_kernel, cudaFuncAttributeMaxDynamicSharedMemorySize,
                         (int)rec_smem);

    dim3 pgrid(Tn * Nn / 64, Hn / 64, Bn);   // (512, 4, 8)
    dim3 rgrid(8, Bn * 2);                    // 128 CTAs = 16 clusters of 8

    // Layer 0
    proj_kernel<<<pgrid, 256>>>(x, wih0, bih0, bhh0);
    rec_kernel<<<rgrid, 128, rec_smem>>>(hx, whh0, nullptr, hn, 0);

    // Layer 1
    proj_kernel<<<pgrid, 256>>>(nullptr, wih1, bih1, bhh1);
    rec_kernel<<<rgrid, 128, rec_smem>>>(hx, whh1, out, hn, 1);
}